// round 6
// baseline (speedup 1.0000x reference)
#include <cuda_runtime.h>

#define B_   256
#define IN_  256
#define OUT_ 512
#define EPS_ 1e-7f

__device__ float g_R[B_ * IN_];        // 1/(x[b,i]+eps)
__device__ float g_relx[IN_ * OUT_];   // rel_x[i][o]
__device__ float g_colsum[IN_];        // sum_b x[b,i], sequential-b order
__device__ int   g_iw[OUT_];           // argmax_i w[i,o]
__device__ float g_wv[OUT_];           // w[iw,o]

// ---------------------------------------------------------------------------
// Kernel 0 (kPre, 88 blocks): 0..63 -> g_R (recips, float4/thread);
// 64..71 -> colsum (32 threads each, exact sequential-b order, batched loads);
// 72..87 -> w-argmax (32 o's per block, 8 i-chunks x 32 lanes, exact merge).
// ---------------------------------------------------------------------------
__global__ void kPre(const float* __restrict__ x, const float* __restrict__ w) {
    const int bid = blockIdx.x;
    const int tid = threadIdx.x;

    if (bid < 64) {
        int e = bid * 256 + tid;                 // float4 index, 16384 total
        float4 xv = ((const float4*)x)[e];
        float4 rv;
        rv.x = 1.0f / (xv.x + EPS_);
        rv.y = 1.0f / (xv.y + EPS_);
        rv.z = 1.0f / (xv.z + EPS_);
        rv.w = 1.0f / (xv.w + EPS_);
        ((float4*)g_R)[e] = rv;
        return;
    }

    if (bid < 72) {
        if (tid < 32) {
            const int i = (bid - 64) * 32 + tid;
            float s = 0.0f;
            #pragma unroll
            for (int c = 0; c < 8; c++) {
                float v[32];
                #pragma unroll
                for (int j = 0; j < 32; j++)
                    v[j] = x[(c * 32 + j) * IN_ + i];
                #pragma unroll
                for (int j = 0; j < 32; j++)
                    s += v[j];
            }
            g_colsum[i] = s;
        }
        return;
    }

    // w-argmax: block handles 32 o's; thread (ic, ol) scans 32 i's
    __shared__ float sv[8][32];
    __shared__ int   si[8][32];

    const int blk = bid - 72;            // 0..15
    const int ol  = tid & 31;
    const int ic  = tid >> 5;
    const int o   = blk * 32 + ol;

    float best = -1.f;
    int   bi   = 0;
    #pragma unroll
    for (int j = 0; j < 32; j++) {
        int i = ic * 32 + j;
        float v = w[i * OUT_ + o];
        if (v > best) { best = v; bi = i; }
    }
    sv[ic][ol] = best;
    si[ic][ol] = bi;
    __syncthreads();

    if (tid < 32) {
        float b  = sv[0][tid];
        int   ix = si[0][tid];
        #pragma unroll
        for (int c = 1; c < 8; c++)
            if (sv[c][tid] > b) { b = sv[c][tid]; ix = si[c][tid]; }
        g_iw[blk * 32 + tid] = ix;
        g_wv[blk * 32 + tid] = b;
    }
}

// ---------------------------------------------------------------------------
// Kernel 1: rel_x[i,o] = (sum_b min(t[b,o]*R[b,i],1)) / colsum[i]
// Tile 32i x 16o, 256 thr (o fastest), 2i x 1o per thread. Grid (8,32)=256.
// Staging is a pure float4 copy of g_R (no MUFU here).
// ---------------------------------------------------------------------------
__global__ void k_relx(const float* __restrict__ t) {
    __shared__ float Rs[128][32];   // [b][i_local]
    __shared__ float Ts[128][16];   // [b][o_local]

    const int i0  = blockIdx.x * 32;
    const int o0  = blockIdx.y * 16;
    const int lid = threadIdx.x;
    const int to  = lid & 15;    // o
    const int tp  = lid >> 4;    // i pair: 2tp, 2tp+1

    float acc0 = 0.f, acc1 = 0.f;

    for (int bb = 0; bb < B_; bb += 128) {
        #pragma unroll
        for (int k = 0; k < 4; k++) {
            int e   = lid + k * 256;
            int row = e >> 3;
            int c4  = (e & 7) * 4;
            *(float4*)&Rs[row][c4] = *(const float4*)&g_R[(bb + row) * IN_ + i0 + c4];
        }
        #pragma unroll
        for (int k = 0; k < 2; k++) {
            int e   = lid + k * 256;
            int row = e >> 2;
            int c4  = (e & 3) * 4;
            *(float4*)&Ts[row][c4] = *(const float4*)&t[(bb + row) * OUT_ + o0 + c4];
        }
        __syncthreads();

        #pragma unroll 8
        for (int b = 0; b < 128; b++) {
            float2 r  = *(const float2*)&Rs[b][2 * tp];
            float  tv = Ts[b][to];
            acc0 += fminf(tv * r.x, 1.0f);
            acc1 += fminf(tv * r.y, 1.0f);
        }
        __syncthreads();
    }

    const int i_0 = i0 + 2 * tp, i_1 = i_0 + 1;
    const int o   = o0 + to;
    g_relx[i_0 * OUT_ + o] = acc0 / g_colsum[i_0];
    g_relx[i_1 * OUT_ + o] = acc1 / g_colsum[i_1];
}

// ---------------------------------------------------------------------------
// Kernel 2: argmax_i x[b,i]*relx[i,o] with fmax-only inner loop, chunk-of-32
// winner tracking, and in-smem equality rescan (exact first-max). Then
// outputs chosen_x and chosen_w. Tile 16b x 32o, 256 thr. Grid (16,16)=256.
// ---------------------------------------------------------------------------
__global__ void k_argmax(const float* __restrict__ x,
                         const float* __restrict__ w,
                         float* __restrict__ outx,
                         float* __restrict__ outw) {
    __shared__ float Xs[128][17];   // [i][b_local] transposed x half-tile
    __shared__ float Rl[128][32];   // [i][o_local] relx half-tile

    const int b0  = blockIdx.x * 16;
    const int o0  = blockIdx.y * 32;
    const int lid = threadIdx.x;
    const int to  = lid & 15;    // o pair: 2to, 2to+1
    const int tb  = lid >> 4;    // b: 0..15

    float best0 = -1.f, best1 = -1.f;
    int   bc0 = 0, bc1 = 0;      // winning chunk base (global i)
    int   id0 = 0, id1 = 0;      // exact winning index

    for (int half = 0; half < 2; half++) {
        const int iz = half * 128;
        #pragma unroll
        for (int k = 0; k < 2; k++) {       // Xs (transposed)
            int e   = lid + k * 256;
            int row = e >> 5;
            int c4  = (e & 31) * 4;
            float4 v = *(const float4*)&x[(b0 + row) * IN_ + iz + c4];
            Xs[c4 + 0][row] = v.x;
            Xs[c4 + 1][row] = v.y;
            Xs[c4 + 2][row] = v.z;
            Xs[c4 + 3][row] = v.w;
        }
        #pragma unroll
        for (int k = 0; k < 4; k++) {       // Rl
            int e   = lid + k * 256;
            int row = e >> 3;
            int c4  = (e & 7) * 4;
            *(float4*)&Rl[row][c4] = *(const float4*)&g_relx[(iz + row) * OUT_ + o0 + c4];
        }
        __syncthreads();

        #pragma unroll
        for (int c = 0; c < 4; c++) {
            float cm0 = -1.f, cm1 = -1.f;
            #pragma unroll
            for (int j = 0; j < 32; j++) {
                int i = c * 32 + j;
                float  xv = Xs[i][tb];
                float2 rv = *(const float2*)&Rl[i][2 * to];
                cm0 = fmaxf(cm0, xv * rv.x);
                cm1 = fmaxf(cm1, xv * rv.y);
            }
            if (cm0 > best0) { best0 = cm0; bc0 = iz + c * 32; }
            if (cm1 > best1) { best1 = cm1; bc1 = iz + c * 32; }
        }

        // In-smem rescan of this half's winning chunk (first-max, exact bits)
        if (bc0 >= iz) {
            const int cl = bc0 - iz;
            #pragma unroll 8
            for (int j = 31; j >= 0; j--) {
                float v = Xs[cl + j][tb] * Rl[cl + j][2 * to];
                if (v == best0) id0 = bc0 + j;
            }
        }
        if (bc1 >= iz) {
            const int cl = bc1 - iz;
            #pragma unroll 8
            for (int j = 31; j >= 0; j--) {
                float v = Xs[cl + j][tb] * Rl[cl + j][2 * to + 1];
                if (v == best1) id1 = bc1 + j;
            }
        }
        __syncthreads();
    }

    const int b  = b0 + tb;
    const int o_ = o0 + 2 * to;

    float2 ox;
    ox.x = x[b * IN_ + id0] * w[id0 * OUT_ + o_];
    ox.y = x[b * IN_ + id1] * w[id1 * OUT_ + o_ + 1];
    *(float2*)&outx[b * OUT_ + o_] = ox;

    int   iw0 = g_iw[o_],  iw1 = g_iw[o_ + 1];
    float wv0 = g_wv[o_],  wv1 = g_wv[o_ + 1];
    float2 ow;
    ow.x = x[b * IN_ + iw0] * wv0;
    ow.y = x[b * IN_ + iw1] * wv1;
    *(float2*)&outw[b * OUT_ + o_] = ow;
}

// ---------------------------------------------------------------------------
extern "C" void kernel_launch(void* const* d_in, const int* in_sizes, int n_in,
                              void* d_out, int out_size) {
    const float* x = (const float*)d_in[0];
    const float* w = (const float*)d_in[1];
    const float* t = (const float*)d_in[2];
    float* outx = (float*)d_out;
    float* outw = (float*)d_out + B_ * OUT_;

    kPre    <<<88, 256>>>(x, w);
    k_relx  <<<dim3(IN_ / 32, OUT_ / 16), 256>>>(t);
    k_argmax<<<dim3(B_  / 16, OUT_ / 32), 256>>>(x, w, outx, outw);
}